// round 15
// baseline (speedup 1.0000x reference)
#include <cuda_runtime.h>

// NeuralDictionary: out = softmax(keys @ query) @ values, + argmax(scores).
// CAPACITY=1e6, D=64. Streaming 512 MB -> HBM-bound.
// CONVERGED FINAL: interleaved float4 striding, half-warp row ownership,
// 4 CTAs/SM, single fused kernel with last-CTA final reduction.
// Triplicate runs (R3/R12/R14): ncu 86.8/90.3/87.3us, HBM 5.7-5.95 TB/s.
// Binding wall is DRAM device bandwidth (~74% of nameplate) for this
// dual-stream once-touched fp32 read mix: occupancy (R3), locality &
// cache-policy (R4), phase-split (R10), load-balance (R11) all falsified;
// LTS/LSU demand is far under their measured caps at NAT clocks.
// Un-shifted exp is safe: |score| <~ 45 << 88 (fp32 exp overflow).

#define CAP        1000000
#define DIM        64
#define NCTA       592          // 4 CTAs/SM x 148 SMs -> exactly 1 wave
#define NWARP      8
#define NTHREADS   256
#define NH         (NCTA * NWARP * 2)   // 9472 half-warps; each owns a row stride

// Scratch (__device__ globals: allocation-free rule)
__device__ float g_acc[NCTA * DIM];
__device__ float g_l  [NCTA];
__device__ float g_bs [NCTA];
__device__ int   g_bi [NCTA];
__device__ int   g_cnt;                 // zero-init; reset by last CTA each call

__global__ __launch_bounds__(NTHREADS, 4)
void nd_fused(const float* __restrict__ query,
              const float* __restrict__ keys,
              const float* __restrict__ values,
              float* __restrict__ out, int out_size)
{
    const int t    = threadIdx.x;
    const int lane = t & 31;
    const int wid  = t >> 5;
    const int half = lane >> 4;          // 0/1: which row of the warp's pair
    const int l16  = lane & 15;          // lane within 16-lane row group

    // global half-warp id: owns rows gh, gh+NH, gh+2NH, ...
    const int gh = (blockIdx.x * NWARP + wid) * 2 + half;

    // lane l16 owns dims 4*l16 .. 4*l16+3 (one float4); row = 16 float4
    const float4  q4 = ((const float4*)query)[l16];
    const float4* __restrict__ kp = (const float4*)keys   + l16;
    const float4* __restrict__ vp = (const float4*)values + l16;

    float4 acc = make_float4(0.f, 0.f, 0.f, 0.f);
    float  lsum = 0.f;
    float  bs = -3.0e38f;
    int    bi = 0;

    int r = gh;
    // 4 rows per half-warp per iter; all 8 LDG.128 issued up front for MLP.
    for (; r + 3 * NH < CAP; r += 4 * NH) {
        const size_t o0 = (size_t)r * 16;            // row stride = 16 float4
        const size_t o1 = o0 + (size_t)NH * 16;
        const size_t o2 = o1 + (size_t)NH * 16;
        const size_t o3 = o2 + (size_t)NH * 16;

        const float4 k0 = __ldg(kp + o0);
        const float4 k1 = __ldg(kp + o1);
        const float4 k2 = __ldg(kp + o2);
        const float4 k3 = __ldg(kp + o3);
        const float4 v0 = __ldg(vp + o0);
        const float4 v1 = __ldg(vp + o1);
        const float4 v2 = __ldg(vp + o2);
        const float4 v3 = __ldg(vp + o3);

        float s0 = k0.x*q4.x + k0.y*q4.y + k0.z*q4.z + k0.w*q4.w;
        float s1 = k1.x*q4.x + k1.y*q4.y + k1.z*q4.z + k1.w*q4.w;
        float s2 = k2.x*q4.x + k2.y*q4.y + k2.z*q4.z + k2.w*q4.w;
        float s3 = k3.x*q4.x + k3.y*q4.y + k3.z*q4.z + k3.w*q4.w;

        #pragma unroll
        for (int off = 8; off; off >>= 1) {          // 16-lane reduce: 4 shfl/row
            s0 += __shfl_xor_sync(0xffffffffu, s0, off);
            s1 += __shfl_xor_sync(0xffffffffu, s1, off);
            s2 += __shfl_xor_sync(0xffffffffu, s2, off);
            s3 += __shfl_xor_sync(0xffffffffu, s3, off);
        }

        const float w0 = __expf(s0);
        const float w1 = __expf(s1);
        const float w2 = __expf(s2);
        const float w3 = __expf(s3);

        lsum += (w0 + w1) + (w2 + w3);
        acc.x += w0*v0.x; acc.y += w0*v0.y; acc.z += w0*v0.z; acc.w += w0*v0.w;
        acc.x += w1*v1.x; acc.y += w1*v1.y; acc.z += w1*v1.z; acc.w += w1*v1.w;
        acc.x += w2*v2.x; acc.y += w2*v2.y; acc.z += w2*v2.z; acc.w += w2*v2.w;
        acc.x += w3*v3.x; acc.y += w3*v3.y; acc.z += w3*v3.z; acc.w += w3*v3.w;

        // rows visited in increasing order; strict '>' keeps smallest index
        if (s0 > bs) { bs = s0; bi = r;          }
        if (s1 > bs) { bs = s1; bi = r + NH;     }
        if (s2 > bs) { bs = s2; bi = r + 2*NH;   }
        if (s3 > bs) { bs = s3; bi = r + 3*NH;   }
    }
    for (; r < CAP; r += NH) {                       // tail
        const size_t o = (size_t)r * 16;
        const float4 k = __ldg(kp + o);
        const float4 v = __ldg(vp + o);
        float s = k.x*q4.x + k.y*q4.y + k.z*q4.z + k.w*q4.w;
        #pragma unroll
        for (int off = 8; off; off >>= 1)
            s += __shfl_xor_sync(0xffffffffu, s, off);
        const float w = __expf(s);
        lsum += w;
        acc.x += w*v.x; acc.y += w*v.y; acc.z += w*v.z; acc.w += w*v.w;
        if (s > bs) { bs = s; bi = r; }
    }

    // ---- CTA reduction (16 half-warp partials) ----
    __shared__ __align__(16) float sAcc[2 * NWARP][DIM];
    __shared__ float sL [2 * NWARP];
    __shared__ float sBs[2 * NWARP];
    __shared__ int   sBi[2 * NWARP];

    const int hw = wid * 2 + half;
    ((float4*)sAcc[hw])[l16] = acc;
    if (l16 == 0) { sL[hw] = lsum; sBs[hw] = bs; sBi[hw] = bi; }
    __syncthreads();

    if (t < DIM) {
        float a = 0.f;
        #pragma unroll
        for (int h = 0; h < 2 * NWARP; ++h) a += sAcc[h][t];
        g_acc[blockIdx.x * DIM + t] = a;
    }
    if (t == 64) {
        float L = 0.f;
        #pragma unroll
        for (int h = 0; h < 2 * NWARP; ++h) L += sL[h];
        g_l[blockIdx.x] = L;
    }
    if (t == 65) {
        float B = -3.0e38f; int Bi = 0;
        #pragma unroll
        for (int h = 0; h < 2 * NWARP; ++h)
            if (sBs[h] > B || (sBs[h] == B && sBi[h] < Bi)) { B = sBs[h]; Bi = sBi[h]; }
        g_bs[blockIdx.x] = B;
        g_bi[blockIdx.x] = Bi;
    }

    // ---- last-CTA final reduction ----
    __threadfence();
    __shared__ int isLast;
    if (t == 0) isLast = (atomicAdd(&g_cnt, 1) == NCTA - 1);
    __syncthreads();
    if (!isLast) return;

    // 64-vector: 4-way split over CTAs, 256 parallel threads (~148 loads each)
    __shared__ float fin[4][DIM];
    __shared__ float finL;
    __shared__ int   finBi;
    {
        const int quarter = t >> 6, d = t & 63;
        float a = 0.f;
        for (int c = quarter; c < NCTA; c += 4) a += g_acc[c * DIM + d];
        fin[quarter][d] = a;
    }
    if (wid == 0) {                                  // warp 0: L reduce
        float L = 0.f;
        for (int c = lane; c < NCTA; c += 32) L += g_l[c];
        #pragma unroll
        for (int off = 16; off; off >>= 1)
            L += __shfl_xor_sync(0xffffffffu, L, off);
        if (lane == 0) finL = L;
    }
    if (wid == 1) {                                  // warp 1: argmax reduce
        float B = -3.0e38f; int Bi = 0;
        for (int c = lane; c < NCTA; c += 32) {
            const float b = g_bs[c]; const int i = g_bi[c];
            if (b > B || (b == B && i < Bi)) { B = b; Bi = i; }
        }
        #pragma unroll
        for (int off = 16; off; off >>= 1) {
            const float ob = __shfl_xor_sync(0xffffffffu, B,  off);
            const int   oi = __shfl_xor_sync(0xffffffffu, Bi, off);
            if (ob > B || (ob == B && oi < Bi)) { B = ob; Bi = oi; }
        }
        if (lane == 0) finBi = Bi;
    }
    __syncthreads();

    if (t < DIM && t < out_size)
        out[t] = (fin[0][t] + fin[1][t] + fin[2][t] + fin[3][t]) / finL;
    if (t == 64 && t < out_size)
        out[64] = (float)finBi;                      // reference's argmax
    if (t > 64 && t < out_size)
        out[t] = 0.f;
    if (t == 0) g_cnt = 0;                           // reset for next graph replay
}

extern "C" void kernel_launch(void* const* d_in, const int* in_sizes, int n_in,
                              void* d_out, int out_size)
{
    const float* query  = (const float*)d_in[0];
    const float* keys   = (const float*)d_in[1];
    const float* values = (const float*)d_in[2];

    nd_fused<<<NCTA, NTHREADS>>>(query, keys, values, (float*)d_out, out_size);
}

// round 16
// speedup vs baseline: 1.0534x; 1.0534x over previous
#include <cuda_runtime.h>

// NeuralDictionary: out = softmax(keys @ query) @ values, + argmax(scores).
// CAPACITY=1e6, D=64. Streaming 512 MB -> HBM-bound.
// CONVERGED FINAL: interleaved float4 striding, half-warp row ownership,
// 4 CTAs/SM, single fused kernel with last-CTA final reduction.
// Quadruplicate identical-source runs (R3/R12/R14/R15): ncu 86.8/90.3/87.3/
// 91.5us, HBM 5.64-5.95 TB/s — spread is NAT-clock/DVFS jitter, not code.
// Binding wall is DRAM device bandwidth (~74% of nameplate) for this
// dual-stream once-touched fp32 read mix: occupancy (R3), locality &
// cache-policy (R4), phase-split (R10), load-balance (R11) all falsified;
// LTS/LSU demand is far under their measured caps; TMA shares the LTS path;
// the 512 MB of traffic is algorithmically irreducible.
// Un-shifted exp is safe: |score| <~ 45 << 88 (fp32 exp overflow).

#define CAP        1000000
#define DIM        64
#define NCTA       592          // 4 CTAs/SM x 148 SMs -> exactly 1 wave
#define NWARP      8
#define NTHREADS   256
#define NH         (NCTA * NWARP * 2)   // 9472 half-warps; each owns a row stride

// Scratch (__device__ globals: allocation-free rule)
__device__ float g_acc[NCTA * DIM];
__device__ float g_l  [NCTA];
__device__ float g_bs [NCTA];
__device__ int   g_bi [NCTA];
__device__ int   g_cnt;                 // zero-init; reset by last CTA each call

__global__ __launch_bounds__(NTHREADS, 4)
void nd_fused(const float* __restrict__ query,
              const float* __restrict__ keys,
              const float* __restrict__ values,
              float* __restrict__ out, int out_size)
{
    const int t    = threadIdx.x;
    const int lane = t & 31;
    const int wid  = t >> 5;
    const int half = lane >> 4;          // 0/1: which row of the warp's pair
    const int l16  = lane & 15;          // lane within 16-lane row group

    // global half-warp id: owns rows gh, gh+NH, gh+2NH, ...
    const int gh = (blockIdx.x * NWARP + wid) * 2 + half;

    // lane l16 owns dims 4*l16 .. 4*l16+3 (one float4); row = 16 float4
    const float4  q4 = ((const float4*)query)[l16];
    const float4* __restrict__ kp = (const float4*)keys   + l16;
    const float4* __restrict__ vp = (const float4*)values + l16;

    float4 acc = make_float4(0.f, 0.f, 0.f, 0.f);
    float  lsum = 0.f;
    float  bs = -3.0e38f;
    int    bi = 0;

    int r = gh;
    // 4 rows per half-warp per iter; all 8 LDG.128 issued up front for MLP.
    for (; r + 3 * NH < CAP; r += 4 * NH) {
        const size_t o0 = (size_t)r * 16;            // row stride = 16 float4
        const size_t o1 = o0 + (size_t)NH * 16;
        const size_t o2 = o1 + (size_t)NH * 16;
        const size_t o3 = o2 + (size_t)NH * 16;

        const float4 k0 = __ldg(kp + o0);
        const float4 k1 = __ldg(kp + o1);
        const float4 k2 = __ldg(kp + o2);
        const float4 k3 = __ldg(kp + o3);
        const float4 v0 = __ldg(vp + o0);
        const float4 v1 = __ldg(vp + o1);
        const float4 v2 = __ldg(vp + o2);
        const float4 v3 = __ldg(vp + o3);

        float s0 = k0.x*q4.x + k0.y*q4.y + k0.z*q4.z + k0.w*q4.w;
        float s1 = k1.x*q4.x + k1.y*q4.y + k1.z*q4.z + k1.w*q4.w;
        float s2 = k2.x*q4.x + k2.y*q4.y + k2.z*q4.z + k2.w*q4.w;
        float s3 = k3.x*q4.x + k3.y*q4.y + k3.z*q4.z + k3.w*q4.w;

        #pragma unroll
        for (int off = 8; off; off >>= 1) {          // 16-lane reduce: 4 shfl/row
            s0 += __shfl_xor_sync(0xffffffffu, s0, off);
            s1 += __shfl_xor_sync(0xffffffffu, s1, off);
            s2 += __shfl_xor_sync(0xffffffffu, s2, off);
            s3 += __shfl_xor_sync(0xffffffffu, s3, off);
        }

        const float w0 = __expf(s0);
        const float w1 = __expf(s1);
        const float w2 = __expf(s2);
        const float w3 = __expf(s3);

        lsum += (w0 + w1) + (w2 + w3);
        acc.x += w0*v0.x; acc.y += w0*v0.y; acc.z += w0*v0.z; acc.w += w0*v0.w;
        acc.x += w1*v1.x; acc.y += w1*v1.y; acc.z += w1*v1.z; acc.w += w1*v1.w;
        acc.x += w2*v2.x; acc.y += w2*v2.y; acc.z += w2*v2.z; acc.w += w2*v2.w;
        acc.x += w3*v3.x; acc.y += w3*v3.y; acc.z += w3*v3.z; acc.w += w3*v3.w;

        // rows visited in increasing order; strict '>' keeps smallest index
        if (s0 > bs) { bs = s0; bi = r;          }
        if (s1 > bs) { bs = s1; bi = r + NH;     }
        if (s2 > bs) { bs = s2; bi = r + 2*NH;   }
        if (s3 > bs) { bs = s3; bi = r + 3*NH;   }
    }
    for (; r < CAP; r += NH) {                       // tail
        const size_t o = (size_t)r * 16;
        const float4 k = __ldg(kp + o);
        const float4 v = __ldg(vp + o);
        float s = k.x*q4.x + k.y*q4.y + k.z*q4.z + k.w*q4.w;
        #pragma unroll
        for (int off = 8; off; off >>= 1)
            s += __shfl_xor_sync(0xffffffffu, s, off);
        const float w = __expf(s);
        lsum += w;
        acc.x += w*v.x; acc.y += w*v.y; acc.z += w*v.z; acc.w += w*v.w;
        if (s > bs) { bs = s; bi = r; }
    }

    // ---- CTA reduction (16 half-warp partials) ----
    __shared__ __align__(16) float sAcc[2 * NWARP][DIM];
    __shared__ float sL [2 * NWARP];
    __shared__ float sBs[2 * NWARP];
    __shared__ int   sBi[2 * NWARP];

    const int hw = wid * 2 + half;
    ((float4*)sAcc[hw])[l16] = acc;
    if (l16 == 0) { sL[hw] = lsum; sBs[hw] = bs; sBi[hw] = bi; }
    __syncthreads();

    if (t < DIM) {
        float a = 0.f;
        #pragma unroll
        for (int h = 0; h < 2 * NWARP; ++h) a += sAcc[h][t];
        g_acc[blockIdx.x * DIM + t] = a;
    }
    if (t == 64) {
        float L = 0.f;
        #pragma unroll
        for (int h = 0; h < 2 * NWARP; ++h) L += sL[h];
        g_l[blockIdx.x] = L;
    }
    if (t == 65) {
        float B = -3.0e38f; int Bi = 0;
        #pragma unroll
        for (int h = 0; h < 2 * NWARP; ++h)
            if (sBs[h] > B || (sBs[h] == B && sBi[h] < Bi)) { B = sBs[h]; Bi = sBi[h]; }
        g_bs[blockIdx.x] = B;
        g_bi[blockIdx.x] = Bi;
    }

    // ---- last-CTA final reduction ----
    __threadfence();
    __shared__ int isLast;
    if (t == 0) isLast = (atomicAdd(&g_cnt, 1) == NCTA - 1);
    __syncthreads();
    if (!isLast) return;

    // 64-vector: 4-way split over CTAs, 256 parallel threads (~148 loads each)
    __shared__ float fin[4][DIM];
    __shared__ float finL;
    __shared__ int   finBi;
    {
        const int quarter = t >> 6, d = t & 63;
        float a = 0.f;
        for (int c = quarter; c < NCTA; c += 4) a += g_acc[c * DIM + d];
        fin[quarter][d] = a;
    }
    if (wid == 0) {                                  // warp 0: L reduce
        float L = 0.f;
        for (int c = lane; c < NCTA; c += 32) L += g_l[c];
        #pragma unroll
        for (int off = 16; off; off >>= 1)
            L += __shfl_xor_sync(0xffffffffu, L, off);
        if (lane == 0) finL = L;
    }
    if (wid == 1) {                                  // warp 1: argmax reduce
        float B = -3.0e38f; int Bi = 0;
        for (int c = lane; c < NCTA; c += 32) {
            const float b = g_bs[c]; const int i = g_bi[c];
            if (b > B || (b == B && i < Bi)) { B = b; Bi = i; }
        }
        #pragma unroll
        for (int off = 16; off; off >>= 1) {
            const float ob = __shfl_xor_sync(0xffffffffu, B,  off);
            const int   oi = __shfl_xor_sync(0xffffffffu, Bi, off);
            if (ob > B || (ob == B && oi < Bi)) { B = ob; Bi = oi; }
        }
        if (lane == 0) finBi = Bi;
    }
    __syncthreads();

    if (t < DIM && t < out_size)
        out[t] = (fin[0][t] + fin[1][t] + fin[2][t] + fin[3][t]) / finL;
    if (t == 64 && t < out_size)
        out[64] = (float)finBi;                      // reference's argmax
    if (t > 64 && t < out_size)
        out[t] = 0.f;
    if (t == 0) g_cnt = 0;                           // reset for next graph replay
}

extern "C" void kernel_launch(void* const* d_in, const int* in_sizes, int n_in,
                              void* d_out, int out_size)
{
    const float* query  = (const float*)d_in[0];
    const float* keys   = (const float*)d_in[1];
    const float* values = (const float*)d_in[2];

    nd_fused<<<NCTA, NTHREADS>>>(query, keys, values, (float*)d_out, out_size);
}